// round 15
// baseline (speedup 1.0000x reference)
#include <cuda_runtime.h>
#include <cuda_bf16.h>

// Problem shape (fixed by dataset):
//   S = 8192, G = 1024, T = 4096 (t0 sorted), E = 16384
//
// out[t, g] = sum over events with start <= t0[t] < end of
//             rate[e] * weights[index[e]], grouped by group_id[index[e]].
//
// Single persistent kernel, difference-array formulation, with the grid
// barriers OVERLAPPED by independent work:
//   Phase 1 (all 512 blocks, 32 events each): binary search; endpoint
//     records bucketed per 8-row chunk + REDG chunk column sums.
//   barrier1
//   Mid section (concurrent):
//     - blocks 0..127: column scan of g_part -> exclusive offsets g_off
//       (chunk-major), zero-restoring g_part.
//     - ALL blocks: build their chunk's 8x1024 diff tile in smem from the
//       records, stage it into 8 float4 REGISTERS. (Depends only on ph.1.)
//   barrier2
//   Tail: one coalesced g_off float4 load + 8 FADD4 + 8 STG.128.
//   Blocks 0,1 then reset g_cnt (post-barrier2: all reads done).
//
// Barrier: monotonic-generation counter, REDG-rate arrivals, VOLATILE-LOAD
// polling (no atomic-RMW poll). All 512 blocks provably co-resident:
// __launch_bounds__(256,4) caps regs at 64 (>=4 blocks/SM), smem 33KB
// (6/SM) -> 592 slots >= 512.

#define T_DIM  4096
#define G_DIM  1024
#define NCH    512            // 8-row chunks
#define CHROWS 8
#define CAP    256            // records per chunk (expected ~64, sigma ~8)
#define GRID   512
#define NTHR   256

// Bank-conflict-breaking bijection on [0,4096): x ^ (x>>5) ^ (x>>10)
#define SWZ(m) ((m) ^ ((m) >> 5) ^ ((m) >> 10))

__device__ unsigned g_bar = 0;           // monotonic barrier counter
__device__ int   g_cnt[NCH];             // bucket counts (zero-invariant)
__device__ uint2 g_rec[NCH][CAP];        // endpoint records, 1 MB
__device__ float g_part[G_DIM][NCH];     // chunk sums (zero-invariant), 2 MB
__device__ float g_off[NCH][G_DIM];      // exclusive offsets, chunk-major, 2 MB

// Monotonic-generation grid barrier; volatile-load poll (no RMW polling).
__device__ __forceinline__ void grid_barrier()
{
    __threadfence();                     // release: my writes visible
    __syncthreads();
    if (threadIdx.x == 0) {
        unsigned gen = atomicAdd(&g_bar, 1u);
        unsigned target = (gen / GRID + 1u) * GRID;
        while (*(volatile unsigned*)&g_bar < target)
            __nanosleep(64);
    }
    __syncthreads();
    __threadfence();                     // acquire side
}

__global__ void __launch_bounds__(NTHR, 4)
fused_kernel(const int* __restrict__ index,
             const float* __restrict__ rate,
             const float* __restrict__ starttime,
             const float* __restrict__ endtime,
             const float* __restrict__ t0,
             const int* __restrict__ group_id,
             const float* __restrict__ weights,
             float* __restrict__ out,
             int E)
{
    __shared__ float smem_buf[CHROWS * G_DIM];   // 32 KB, reused per phase
    int tid = threadIdx.x;
    int bid = blockIdx.x;

    // ---------------- Phase 1: search + bucket (all blocks) ----------------
    {
        for (int i = tid; i < T_DIM; i += NTHR)
            smem_buf[SWZ(i)] = t0[i];

        int evpb = (E + GRID - 1) / GRID;        // 32 for E=16384
        int e = bid * evpb + tid;
        bool valid = (tid < evpb) && (e < E);

        float st = 0.f, en = 0.f, w = 0.f;
        int g = 0;
        if (valid) {
            st = starttime[e];
            en = endtime[e];
            int src = index[e];
            w  = rate[e] * weights[src];
            g  = group_id[src];
        }
        __syncthreads();

        if (valid) {
            // two exact lower_bounds, interleaved for ILP-2
            int lo = 0, hi = T_DIM, lo2 = 0, hi2 = T_DIM;
            while (lo < hi && lo2 < hi2) {
                int m1 = (lo + hi) >> 1;
                int m2 = (lo2 + hi2) >> 1;
                float a = smem_buf[SWZ(m1)];
                float b = smem_buf[SWZ(m2)];
                if (a < st) lo = m1 + 1; else hi = m1;
                if (b < en) lo2 = m2 + 1; else hi2 = m2;
            }
            while (lo < hi) {
                int m = (lo + hi) >> 1;
                if (smem_buf[SWZ(m)] < st) lo = m + 1; else hi = m;
            }
            while (lo2 < hi2) {
                int m = (lo2 + hi2) >> 1;
                if (smem_buf[SWZ(m)] < en) lo2 = m + 1; else hi2 = m;
            }
            if (lo < lo2) {                      // active range [lo, lo2)
                {
                    int c = lo >> 3, r = lo & 7;
                    int pos = atomicAdd(&g_cnt[c], 1);
                    if (pos < CAP) {
                        atomicAdd(&g_part[g][c], w);
                        g_rec[c][pos] = make_uint2((unsigned)((r << 10) | g),
                                                   __float_as_uint(w));
                    }
                }
                if (lo2 < T_DIM) {
                    int c = lo2 >> 3, r = lo2 & 7;
                    int pos = atomicAdd(&g_cnt[c], 1);
                    if (pos < CAP) {
                        atomicAdd(&g_part[g][c], -w);
                        g_rec[c][pos] = make_uint2((unsigned)((r << 10) | g),
                                                   __float_as_uint(-w));
                    }
                }
            }
        }
    }

    grid_barrier();   // records + chunk sums complete

    // ------------- Mid: phase 2 (blocks 0..127) -------------
    if (bid < 128) {
        int warp = tid >> 5;
        int lane = tid & 31;
        int gbase = bid * 8;
        int g = gbase + warp;                    // warp = one column

        // lane owns chunks [lane*16, lane*16+16)
        float4* base = (float4*)&g_part[g][lane * 16];
        float v[16];
        #pragma unroll
        for (int q = 0; q < 4; q++) {
            float4 x = base[q];
            v[q*4+0] = x.x; v[q*4+1] = x.y; v[q*4+2] = x.z; v[q*4+3] = x.w;
        }
        float4 z4 = make_float4(0.f, 0.f, 0.f, 0.f);
        #pragma unroll
        for (int q = 0; q < 4; q++) base[q] = z4;   // restore zero inv.

        float tot = 0.f;
        #pragma unroll
        for (int i = 0; i < 16; i++) tot += v[i];
        float acc = tot;
        #pragma unroll
        for (int off = 1; off < 32; off <<= 1) {
            float up = __shfl_up_sync(0xFFFFFFFFu, acc, off);
            if (lane >= off) acc += up;
        }
        float run = acc - tot;                   // exclusive prefix of lane sums

        // stride-13 padded transpose tile (conflict-free)
        #pragma unroll
        for (int i = 0; i < 16; i++) {
            smem_buf[(lane * 16 + i) * 13 + warp] = run;
            run += v[i];
        }
        __syncthreads();

        // transposed write: thread t -> chunks 2t, 2t+1
        #pragma unroll
        for (int k = 0; k < 2; k++) {
            int c2 = tid * 2 + k;
            const float* row = &smem_buf[c2 * 13];
            *(float4*)&g_off[c2][gbase]     = make_float4(row[0], row[1],
                                                          row[2], row[3]);
            *(float4*)&g_off[c2][gbase + 4] = make_float4(row[4], row[5],
                                                          row[6], row[7]);
        }
        __syncthreads();                         // before smem reuse below
    }

    // ------------- Mid: tile build for my chunk (ALL blocks) -------------
    // Depends only on phase 1 -> overlaps the phase-2 work / barrier wait.
    float4 vt[CHROWS];
    {
        int c = bid;                             // chunk == block
        float4* t4 = (float4*)smem_buf;
        #pragma unroll
        for (int i = 0; i < 8; i++)
            t4[i * NTHR + tid] = make_float4(0.f, 0.f, 0.f, 0.f);
        __syncthreads();

        int n = g_cnt[c];
        if (n > CAP) n = CAP;
        for (int i = tid; i < n; i += NTHR) {
            uint2 rec = g_rec[c][i];
            int r = rec.x >> 10;
            int g = rec.x & 1023;
            atomicAdd(&smem_buf[r * G_DIM + g], __uint_as_float(rec.y));
        }
        __syncthreads();

        #pragma unroll
        for (int r = 0; r < CHROWS; r++)
            vt[r] = t4[r * NTHR + tid];          // stage tile into registers
    }

    grid_barrier();   // offsets ready; tiles already in registers

    // ---------------- Tail: seed, prefix, store ----------------
    {
        int c = bid;
        float4 run = *(const float4*)&g_off[c][4 * tid];
        float4* dst = (float4*)out + (size_t)c * CHROWS * (G_DIM / 4) + tid;
        #pragma unroll
        for (int r = 0; r < CHROWS; r++) {
            run.x += vt[r].x; run.y += vt[r].y;
            run.z += vt[r].z; run.w += vt[r].w;
            dst[r * (G_DIM / 4)] = run;
        }
    }

    // Reset bucket counters for next replay (all g_cnt reads happened
    // before barrier2; same-stream ordering protects the next launch).
    if (bid < 2) {
        int c = bid * NTHR + tid;
        g_cnt[c] = 0;
    }
}

// ---------------------------------------------------------------------------
extern "C" void kernel_launch(void* const* d_in, const int* in_sizes, int n_in,
                              void* d_out, int out_size)
{
    const int*   index     = (const int*)  d_in[0];
    const float* rate      = (const float*)d_in[1];
    const float* starttime = (const float*)d_in[2];
    const float* endtime   = (const float*)d_in[3];
    const float* t0        = (const float*)d_in[4];
    const int*   group_id  = (const int*)  d_in[5];
    const float* weights   = (const float*)d_in[6];

    int E = in_sizes[0];

    fused_kernel<<<GRID, NTHR>>>(index, rate, starttime, endtime,
                                 t0, group_id, weights, (float*)d_out, E);
}